// round 6
// baseline (speedup 1.0000x reference)
#include <cuda_runtime.h>
#include <math.h>

static constexpr int NN = 100000;   // nodes (capacity)
static constexpr int EE = 1600000;  // edges (capacity)
static constexpr int DD = 64;
static constexpr int SCAN_B = 1024;
static constexpr int NB_MAX = (NN + SCAN_B - 1) / SCAN_B;

// Scratch (static device globals; no allocation anywhere)
__device__ __align__(16) float g_z[(size_t)NN * DD];   // 25.6 MB z accumulator
__device__ float g_as[NN], g_ad[NN];                   // per-node logit halves
__device__ int   g_cnt[NN];                            // in-degree histogram
__device__ int   g_off[NN];                            // CSR row start
__device__ int   g_pos[NN];                            // scatter cursor -> row end
__device__ int   g_src2[EE];                           // src permuted into dst-CSR order
__device__ int   g_bsum[NB_MAX];                       // block sums for scan

// ---------------------------------------------------------------------------
__global__ void k_init(int n) {
    int i = blockIdx.x * blockDim.x + threadIdx.x;
    if (i < n) g_cnt[i] = 0;
}

// K1: per-node a_s = h[n].wh[0:64], a_d = h[n].wh[64:128]  (warp/node)
__global__ void k_node(const float* __restrict__ h, const float* __restrict__ wh, int n) {
    int gt = blockIdx.x * blockDim.x + threadIdx.x;
    int w = gt >> 5, lane = gt & 31;
    if (w >= n) return;
    float2 hv = *reinterpret_cast<const float2*>(h + (size_t)w * DD + lane * 2);
    float2 wa = *reinterpret_cast<const float2*>(wh + lane * 2);
    float2 wb = *reinterpret_cast<const float2*>(wh + DD + lane * 2);
    float ps = hv.x * wa.x + hv.y * wa.y;
    float pd = hv.x * wb.x + hv.y * wb.y;
#pragma unroll
    for (int o = 16; o; o >>= 1) {
        ps += __shfl_xor_sync(0xffffffffu, ps, o);
        pd += __shfl_xor_sync(0xffffffffu, pd, o);
    }
    if (lane == 0) { g_as[w] = ps; g_ad[w] = pd; }
}

// K2: histogram of dst
__global__ void k_hist(const int* __restrict__ dst, int e) {
    int i = blockIdx.x * blockDim.x + threadIdx.x;
    if (i < e) atomicAdd(&g_cnt[dst[i]], 1);
}

// K3a/b/c: multi-block exclusive scan  g_cnt -> g_off, g_pos
__global__ void k_blocksum(int n) {
    __shared__ int sh[SCAN_B];
    int i = blockIdx.x * SCAN_B + threadIdx.x;
    sh[threadIdx.x] = (i < n) ? g_cnt[i] : 0;
    __syncthreads();
#pragma unroll
    for (int s = SCAN_B / 2; s > 0; s >>= 1) {
        if (threadIdx.x < s) sh[threadIdx.x] += sh[threadIdx.x + s];
        __syncthreads();
    }
    if (threadIdx.x == 0) g_bsum[blockIdx.x] = sh[0];
}
__global__ void k_scanb(int nb) {
    __shared__ int sh[128];
    int t = threadIdx.x;
    int v = (t < nb) ? g_bsum[t] : 0;
    sh[t] = v;
    __syncthreads();
#pragma unroll
    for (int d = 1; d < 128; d <<= 1) {
        int u = (t >= d) ? sh[t - d] : 0;
        __syncthreads();
        sh[t] += u;
        __syncthreads();
    }
    if (t < nb) g_bsum[t] = sh[t] - v;
}
__global__ void k_apply(int n) {
    __shared__ int sh[SCAN_B];
    int i = blockIdx.x * SCAN_B + threadIdx.x;
    int v = (i < n) ? g_cnt[i] : 0;
    sh[threadIdx.x] = v;
    __syncthreads();
#pragma unroll
    for (int d = 1; d < SCAN_B; d <<= 1) {
        int u = (threadIdx.x >= d) ? sh[threadIdx.x - d] : 0;
        __syncthreads();
        sh[threadIdx.x] += u;
        __syncthreads();
    }
    if (i < n) {
        int off = g_bsum[blockIdx.x] + sh[threadIdx.x] - v;
        g_off[i] = off;
        g_pos[i] = off;
    }
}

// K4: CSR scatter of src by dst (only 1 scattered 4B write per edge)
__global__ void k_scatter(const int* __restrict__ src, const int* __restrict__ dst, int e) {
    int i = blockIdx.x * blockDim.x + threadIdx.x;
    if (i >= e) return;
    int pos = atomicAdd(&g_pos[dst[i]], 1);
    g_src2[pos] = src[i];
}

// ---------------------------------------------------------------------------
// Online-softmax state (all lanes hold identical scalars; acc is per-lane 2 dims)
struct OS {
    float mf, sf, mt, st;
    float2 aF, aT;
};

__device__ __forceinline__ void os_init(OS& o) {
    o.mf = -INFINITY; o.sf = 0.f; o.mt = -INFINITY; o.st = 0.f;
    o.aF = make_float2(0.f, 0.f); o.aT = make_float2(0.f, 0.f);
}

__device__ __forceinline__ void os_edge(OS& o, const float* __restrict__ tax,
                                        const float* __restrict__ h,
                                        float2 td, float adv, int lane, int s) {
    float2 ts = *reinterpret_cast<const float2*>(tax + (size_t)s * DD + lane * 2);
    float2 hv = *reinterpret_cast<const float2*>(h + (size_t)s * DD + lane * 2);
    float p = ts.x * td.x + ts.y * td.y;
#pragma unroll
    for (int off = 16; off; off >>= 1) p += __shfl_xor_sync(0xffffffffu, p, off);
    float x = g_as[s] + adv;
    float wf = x >= 0.f ? x : 0.01f * x;        // leaky_relu(0.01)
    // f-softmax online update
    float nm = fmaxf(o.mf, wf);
    float sc = __expf(o.mf - nm);
    float ee = __expf(wf - nm);
    o.sf = o.sf * sc + ee;
    o.aF.x = o.aF.x * sc + ee * hv.x;
    o.aF.y = o.aF.y * sc + ee * hv.y;
    o.mf = nm;
    // t-softmax online update
    float nmt = fmaxf(o.mt, p);
    float sct = __expf(o.mt - nmt);
    float et = __expf(p - nmt);
    o.st = o.st * sct + et;
    o.aT.x = o.aT.x * sct + et * hv.x;
    o.aT.y = o.aT.y * sct + et * hv.y;
    o.mt = nmt;
}

// K5: fused segment pass — logits + softmax + weighted aggregation, one sweep
__global__ void k_seg(const float* __restrict__ tax, const float* __restrict__ h, int n) {
    int gt = blockIdx.x * blockDim.x + threadIdx.x;
    int w = gt >> 5, lane = gt & 31;
    if (w >= n) return;
    int r0 = g_off[w], r1 = g_pos[w];   // cursor == segment end after scatter
    float2 z = make_float2(0.f, 0.f);
    if (r1 > r0) {
        float2 td = *reinterpret_cast<const float2*>(tax + (size_t)w * DD + lane * 2);
        float adv = g_ad[w];
        OS o0, o1;
        os_init(o0);
        os_init(o1);
        int j = r0;
        for (; j + 2 <= r1; j += 2) {
            int s0 = g_src2[j], s1 = g_src2[j + 1];
            os_edge(o0, tax, h, td, adv, lane, s0);
            os_edge(o1, tax, h, td, adv, lane, s1);
        }
        if (j < r1) os_edge(o0, tax, h, td, adv, lane, g_src2[j]);
        // merge chains (o0 has >=1 edge, so o0.mf/mt finite)
        float mF = fmaxf(o0.mf, o1.mf);
        float e0 = __expf(o0.mf - mF), e1 = __expf(o1.mf - mF);
        float sf = o0.sf * e0 + o1.sf * e1;
        float ax = o0.aF.x * e0 + o1.aF.x * e1;
        float ay = o0.aF.y * e0 + o1.aF.y * e1;
        float mT = fmaxf(o0.mt, o1.mt);
        float t0 = __expf(o0.mt - mT), t1 = __expf(o1.mt - mT);
        float st = o0.st * t0 + o1.st * t1;
        float bx = o0.aT.x * t0 + o1.aT.x * t1;
        float by = o0.aT.y * t0 + o1.aT.y * t1;
        float isf = 0.5f / sf, ist = 0.5f / st;
        z.x = ax * isf + bx * ist;
        z.y = ay * isf + by * ist;
    }
    *reinterpret_cast<float2*>(g_z + (size_t)w * DD + lane * 2) = z;
}

// ---------------------------------------------------------------------------
// K6: out = z @ W^T + b   (block = (64,4); W transposed in smem, conflict-free)
__global__ void k_out(const float* __restrict__ Ww, const float* __restrict__ Wb,
                      float* __restrict__ out, int n) {
    __shared__ float Ws[DD * DD];   // Ws[k*64 + c] = Ww[c*64 + k]
    __shared__ float bs[DD];
    int tid = threadIdx.y * 64 + threadIdx.x;
    for (int i = tid; i < DD * DD; i += 256) {
        int c = i >> 6, k = i & 63;
        Ws[k * DD + c] = Ww[i];
    }
    if (tid < DD) bs[tid] = Wb[tid];
    __syncthreads();
    int row = blockIdx.x * 4 + threadIdx.y;
    if (row >= n) return;
    int c = threadIdx.x;
    const float* zr = g_z + (size_t)row * DD;
    float acc = bs[c];
#pragma unroll
    for (int k = 0; k < DD; k += 4) {
        float4 zv = *reinterpret_cast<const float4*>(zr + k);
        acc += zv.x * Ws[(k + 0) * DD + c];
        acc += zv.y * Ws[(k + 1) * DD + c];
        acc += zv.z * Ws[(k + 2) * DD + c];
        acc += zv.w * Ws[(k + 3) * DD + c];
    }
    out[(size_t)row * DD + c] = acc;
}

// ---------------------------------------------------------------------------
extern "C" void kernel_launch(void* const* d_in, const int* in_sizes, int n_in,
                              void* d_out, int out_size) {
    const float* h   = (const float*)d_in[0];
    const float* tax = (const float*)d_in[1];
    const int*   src = (const int*)d_in[2];
    const int*   dst = (const int*)d_in[3];
    const float* wh  = (const float*)d_in[4];
    const float* Ww  = (const float*)d_in[5];
    const float* Wb  = (const float*)d_in[6];
    float* out = (float*)d_out;

    int n = in_sizes[0] / DD;
    int e = in_sizes[2];
    int nb = (n + SCAN_B - 1) / SCAN_B;

    k_init<<<(n + 255) / 256, 256>>>(n);
    k_node<<<(int)(((long long)n * 32 + 255) / 256), 256>>>(h, wh, n);
    k_hist<<<(e + 255) / 256, 256>>>(dst, e);
    k_blocksum<<<nb, SCAN_B>>>(n);
    k_scanb<<<1, 128>>>(nb);
    k_apply<<<nb, SCAN_B>>>(n);
    k_scatter<<<(e + 255) / 256, 256>>>(src, dst, e);
    k_seg<<<(int)(((long long)n * 32 + 255) / 256), 256>>>(tax, h, n);
    k_out<<<(n + 3) / 4, dim3(64, 4)>>>(Ww, Wb, out, n);
}

// round 7
// speedup vs baseline: 1.0133x; 1.0133x over previous
#include <cuda_runtime.h>
#include <math.h>

static constexpr int NN = 100000;   // nodes (capacity)
static constexpr int EE = 1600000;  // edges (capacity)
static constexpr int DD = 64;
static constexpr int SCAN_B = 1024;
static constexpr int NB_MAX = (NN + SCAN_B - 1) / SCAN_B;

// Scratch (static device globals; no allocation anywhere)
__device__ __align__(16) float  g_z[(size_t)NN * DD];  // 25.6 MB z result
__device__ float g_as[NN], g_ad[NN];                   // per-node logit halves
__device__ int   g_cnt[NN];                            // in-degree histogram
__device__ int   g_off[NN];                            // CSR row start
__device__ int   g_pos[NN];                            // scatter cursor -> row end
__device__ int   g_mf[NN], g_mt[NN];                   // ordered-int segment maxes
__device__ float g_sf[NN], g_st[NN];                   // softmax denominators
__device__ float g_ef[EE], g_et[EE];                   // logits (original edge order)
__device__ __align__(8) float2 g_e2[EE];               // (e_f, e_t) in CSR order
__device__ int   g_src2[EE];                           // src in CSR order
__device__ int   g_bsum[NB_MAX];                       // block sums for scan

__device__ __forceinline__ int ord(float f) {
    int i = __float_as_int(f);
    return i >= 0 ? i : (i ^ 0x7fffffff);
}
__device__ __forceinline__ float unord(int i) {
    return __int_as_float(i >= 0 ? i : (i ^ 0x7fffffff));
}

// ---------------------------------------------------------------------------
// K1: fused init + per-node dots a_s = h.wh[0:64], a_d = h.wh[64:128]
__global__ void k_nodeinit(const float* __restrict__ h, const float* __restrict__ wh, int n) {
    int gt = blockIdx.x * blockDim.x + threadIdx.x;
    if (gt < n) {
        g_cnt[gt] = 0;
        g_sf[gt] = 0.f;
        g_st[gt] = 0.f;
        int m = ord(-INFINITY);
        g_mf[gt] = m;
        g_mt[gt] = m;
    }
    int w = gt >> 5, lane = gt & 31;
    if (w >= n) return;
    float2 hv = *reinterpret_cast<const float2*>(h + (size_t)w * DD + lane * 2);
    float2 wa = *reinterpret_cast<const float2*>(wh + lane * 2);
    float2 wb = *reinterpret_cast<const float2*>(wh + DD + lane * 2);
    float ps = hv.x * wa.x + hv.y * wa.y;
    float pd = hv.x * wb.x + hv.y * wb.y;
#pragma unroll
    for (int o = 16; o; o >>= 1) {
        ps += __shfl_xor_sync(0xffffffffu, ps, o);
        pd += __shfl_xor_sync(0xffffffffu, pd, o);
    }
    if (lane == 0) { g_as[w] = ps; g_ad[w] = pd; }
}

// K2: histogram of dst
__global__ void k_hist(const int* __restrict__ dst, int e) {
    int i = blockIdx.x * blockDim.x + threadIdx.x;
    if (i < e) atomicAdd(&g_cnt[dst[i]], 1);
}

// K3a: per-block sums of g_cnt
__global__ void k_blocksum(int n) {
    __shared__ int sh[SCAN_B];
    int i = blockIdx.x * SCAN_B + threadIdx.x;
    sh[threadIdx.x] = (i < n) ? g_cnt[i] : 0;
    __syncthreads();
#pragma unroll
    for (int s = SCAN_B / 2; s > 0; s >>= 1) {
        if (threadIdx.x < s) sh[threadIdx.x] += sh[threadIdx.x + s];
        __syncthreads();
    }
    if (threadIdx.x == 0) g_bsum[blockIdx.x] = sh[0];
}

// K4 (PROFILED SLOT): per-edge logits, fully edge-parallel, contiguous writes
__global__ void k_logits(const float* __restrict__ tax, const int* __restrict__ src,
                         const int* __restrict__ dst, int e) {
    int gt = blockIdx.x * blockDim.x + threadIdx.x;
    int w = gt >> 3, l = gt & 7;
    if (w >= e) return;
    int s = src[w], d = dst[w];
    const float4* ts = reinterpret_cast<const float4*>(tax + (size_t)s * DD);
    const float4* td = reinterpret_cast<const float4*>(tax + (size_t)d * DD);
    float4 a0 = ts[l * 2],     b0 = td[l * 2];
    float4 a1 = ts[l * 2 + 1], b1 = td[l * 2 + 1];
    float p = a0.x * b0.x + a0.y * b0.y + a0.z * b0.z + a0.w * b0.w
            + a1.x * b1.x + a1.y * b1.y + a1.z * b1.z + a1.w * b1.w;
#pragma unroll
    for (int o = 4; o; o >>= 1) p += __shfl_xor_sync(0xffffffffu, p, o);
    if (l == 0) {
        float x = g_as[s] + g_ad[d];
        float wf = x >= 0.f ? x : 0.01f * x;     // leaky_relu(0.01)
        g_ef[w] = wf;
        g_et[w] = p;
        atomicMax(&g_mf[d], ord(wf));
        atomicMax(&g_mt[d], ord(p));
    }
}

// K5: exclusive scan of block sums (single tiny block; nb <= 128)
__global__ void k_scanb(int nb) {
    __shared__ int sh[128];
    int t = threadIdx.x;
    int v = (t < nb) ? g_bsum[t] : 0;
    sh[t] = v;
    __syncthreads();
#pragma unroll
    for (int d = 1; d < 128; d <<= 1) {
        int u = (t >= d) ? sh[t - d] : 0;
        __syncthreads();
        sh[t] += u;
        __syncthreads();
    }
    if (t < nb) g_bsum[t] = sh[t] - v;
}

// K6: in-block exclusive scan + block prefix -> g_off, g_pos
__global__ void k_apply(int n) {
    __shared__ int sh[SCAN_B];
    int i = blockIdx.x * SCAN_B + threadIdx.x;
    int v = (i < n) ? g_cnt[i] : 0;
    sh[threadIdx.x] = v;
    __syncthreads();
#pragma unroll
    for (int d = 1; d < SCAN_B; d <<= 1) {
        int u = (threadIdx.x >= d) ? sh[threadIdx.x - d] : 0;
        __syncthreads();
        sh[threadIdx.x] += u;
        __syncthreads();
    }
    if (i < n) {
        int off = g_bsum[blockIdx.x] + sh[threadIdx.x] - v;
        g_off[i] = off;
        g_pos[i] = off;
    }
}

// K7: exp + segment sums (atomics) + CSR scatter of (e_f,e_t) and src
__global__ void k_expscatter(const int* __restrict__ src, const int* __restrict__ dst, int e) {
    int i = blockIdx.x * blockDim.x + threadIdx.x;
    if (i >= e) return;
    int d = dst[i];
    float ef = __expf(g_ef[i] - unord(g_mf[d]));
    float et = __expf(g_et[i] - unord(g_mt[d]));
    atomicAdd(&g_sf[d], ef);
    atomicAdd(&g_st[d], et);
    int pos = atomicAdd(&g_pos[d], 1);
    g_e2[pos] = make_float2(ef, et);
    g_src2[pos] = src[i];
}

// K8: segment aggregation — pure gather + FMA (alpha inline, no shuffles)
__global__ void k_seg(const float* __restrict__ h, int n) {
    int gt = blockIdx.x * blockDim.x + threadIdx.x;
    int w = gt >> 5, lane = gt & 31;
    if (w >= n) return;
    int r0 = g_off[w], r1 = g_pos[w];   // cursor == segment end after scatter
    float2 acc = make_float2(0.f, 0.f);
    if (r1 > r0) {
        float isf = 0.5f / g_sf[w], ist = 0.5f / g_st[w];
        int j = r0;
#pragma unroll 1
        for (; j + 4 <= r1; j += 4) {
            float2 e0 = g_e2[j],     e1 = g_e2[j + 1];
            float2 e2 = g_e2[j + 2], e3 = g_e2[j + 3];
            int s0 = g_src2[j],     s1 = g_src2[j + 1];
            int s2 = g_src2[j + 2], s3 = g_src2[j + 3];
            float a0 = e0.x * isf + e0.y * ist;
            float a1 = e1.x * isf + e1.y * ist;
            float a2 = e2.x * isf + e2.y * ist;
            float a3 = e3.x * isf + e3.y * ist;
            float2 h0 = *reinterpret_cast<const float2*>(h + (size_t)s0 * DD + lane * 2);
            float2 h1 = *reinterpret_cast<const float2*>(h + (size_t)s1 * DD + lane * 2);
            float2 h2 = *reinterpret_cast<const float2*>(h + (size_t)s2 * DD + lane * 2);
            float2 h3 = *reinterpret_cast<const float2*>(h + (size_t)s3 * DD + lane * 2);
            acc.x += a0 * h0.x + a1 * h1.x + a2 * h2.x + a3 * h3.x;
            acc.y += a0 * h0.y + a1 * h1.y + a2 * h2.y + a3 * h3.y;
        }
        for (; j < r1; j++) {
            float2 ev = g_e2[j];
            float a = ev.x * isf + ev.y * ist;
            int s = g_src2[j];
            float2 hv = *reinterpret_cast<const float2*>(h + (size_t)s * DD + lane * 2);
            acc.x += a * hv.x;
            acc.y += a * hv.y;
        }
    }
    *reinterpret_cast<float2*>(g_z + (size_t)w * DD + lane * 2) = acc;
}

// K9: out = z @ W^T + b   (block = (64,4); W transposed in smem, conflict-free)
__global__ void k_out(const float* __restrict__ Ww, const float* __restrict__ Wb,
                      float* __restrict__ out, int n) {
    __shared__ float Ws[DD * DD];   // Ws[k*64 + c] = Ww[c*64 + k]
    __shared__ float bs[DD];
    int tid = threadIdx.y * 64 + threadIdx.x;
    for (int i = tid; i < DD * DD; i += 256) {
        int c = i >> 6, k = i & 63;
        Ws[k * DD + c] = Ww[i];
    }
    if (tid < DD) bs[tid] = Wb[tid];
    __syncthreads();
    int row = blockIdx.x * 4 + threadIdx.y;
    if (row >= n) return;
    int c = threadIdx.x;
    const float* zr = g_z + (size_t)row * DD;
    float acc = bs[c];
#pragma unroll
    for (int k = 0; k < DD; k += 4) {
        float4 zv = *reinterpret_cast<const float4*>(zr + k);
        acc += zv.x * Ws[(k + 0) * DD + c];
        acc += zv.y * Ws[(k + 1) * DD + c];
        acc += zv.z * Ws[(k + 2) * DD + c];
        acc += zv.w * Ws[(k + 3) * DD + c];
    }
    out[(size_t)row * DD + c] = acc;
}

// ---------------------------------------------------------------------------
extern "C" void kernel_launch(void* const* d_in, const int* in_sizes, int n_in,
                              void* d_out, int out_size) {
    const float* h   = (const float*)d_in[0];
    const float* tax = (const float*)d_in[1];
    const int*   src = (const int*)d_in[2];
    const int*   dst = (const int*)d_in[3];
    const float* wh  = (const float*)d_in[4];
    const float* Ww  = (const float*)d_in[5];
    const float* Wb  = (const float*)d_in[6];
    float* out = (float*)d_out;

    int n = in_sizes[0] / DD;
    int e = in_sizes[2];
    int nb = (n + SCAN_B - 1) / SCAN_B;

    // NOTE: launch order arranged so the heavy gather kernel is 4th (ncu slot)
    k_nodeinit<<<(int)(((long long)n * 32 + 255) / 256), 256>>>(h, wh, n);          // 1
    k_hist<<<(e + 255) / 256, 256>>>(dst, e);                                       // 2
    k_blocksum<<<nb, SCAN_B>>>(n);                                                  // 3
    k_logits<<<(int)(((long long)e * 8 + 255) / 256), 256>>>(tax, src, dst, e);     // 4 <- profiled
    k_scanb<<<1, 128>>>(nb);                                                        // 5
    k_apply<<<nb, SCAN_B>>>(n);                                                     // 6
    k_expscatter<<<(e + 255) / 256, 256>>>(src, dst, e);                            // 7
    k_seg<<<(int)(((long long)n * 32 + 255) / 256), 256>>>(h, n);                   // 8
    k_out<<<(n + 3) / 4, dim3(64, 4)>>>(Ww, Wb, out, n);                            // 9
}